// round 1
// baseline (speedup 1.0000x reference)
#include <cuda_runtime.h>

#define Bn 2
#define CSn 128
#define CDn 128
#define SDn 8
#define SHn 16
#define SWn 16
#define DDn 16
#define DHn 32
#define DWn 32
#define Pn  (DDn*DHn*DWn)      /* 16384 */
#define Gn 8
#define K3n 27
#define CGn 16                 /* CS/G */
#define NOFF (K3n*3*Gn)        /* 648 */

// -------- device scratch (allocation-free rule: __device__ globals) --------
__device__ float g_src_cl[Bn*SDn*SHn*SWn*CSn];   // [b][z][y][x][c]
__device__ float g_up_cl[Bn*Pn*CSn];             // [b][p][c]   (channels-last)
__device__ float g_off[Bn*NOFF*Pn];              // [b][o][p]
__device__ float g_wofft[256*NOFF];              // [c][o]
__device__ float g_ws[Gn*K3n*CGn*CDn];           // [g][k][cg][o]

// -------- prep transposes --------
__global__ void k_transpose_src(const float* __restrict__ src) {
    int i = blockIdx.x * blockDim.x + threadIdx.x;
    const int N = Bn*SDn*SHn*SWn*CSn;
    if (i >= N) return;
    int c = i % CSn;
    int s = (i / CSn) % (SDn*SHn*SWn);
    int b = i / (CSn*SDn*SHn*SWn);
    g_src_cl[i] = src[(b*CSn + c)*(SDn*SHn*SWn) + s];
}

__global__ void k_transpose_woff(const float* __restrict__ w) { // w:[648][256]
    int i = blockIdx.x * blockDim.x + threadIdx.x;
    if (i >= 256*NOFF) return;
    int o = i % NOFF;
    int c = i / NOFF;
    g_wofft[i] = w[o*256 + c];
}

__global__ void k_transpose_wdcn(const float* __restrict__ w) { // w:[o][c][27]
    int i = blockIdx.x * blockDim.x + threadIdx.x;
    if (i >= Gn*K3n*CGn*CDn) return;
    int o  = i % CDn;
    int cg = (i / CDn) % CGn;
    int k  = (i / (CDn*CGn)) % K3n;
    int g  = i / (CDn*CGn*K3n);
    g_ws[i] = w[(o*CSn + g*CGn + cg)*K3n + k];
}

// -------- trilinear 2x upsample (half-pixel, edge-clamped == jax resize) ----
__global__ void k_upsample() {
    int bp = blockIdx.x;                 // Bn*Pn blocks
    int b = bp / Pn;
    int p = bp % Pn;
    int d = p >> 10, h = (p >> 5) & 31, w = p & 31;

    float zc = d*0.5f - 0.25f, yc = h*0.5f - 0.25f, xc = w*0.5f - 0.25f;
    int zf = (int)floorf(zc), yf = (int)floorf(yc), xf = (int)floorf(xc);
    float fz = zc - zf, fy = yc - yf, fx = xc - xf;
    int z0 = min(max(zf,     0), SDn-1), z1 = min(max(zf + 1, 0), SDn-1);
    int y0 = min(max(yf,     0), SHn-1), y1 = min(max(yf + 1, 0), SHn-1);
    int x0 = min(max(xf,     0), SWn-1), x1 = min(max(xf + 1, 0), SWn-1);

    const float* base = g_src_cl + (size_t)b * (SDn*SHn*SWn) * CSn;
    int c = threadIdx.x;  // 128

    float v000 = base[(z0*256 + y0*16 + x0)*CSn + c];
    float v001 = base[(z0*256 + y0*16 + x1)*CSn + c];
    float v010 = base[(z0*256 + y1*16 + x0)*CSn + c];
    float v011 = base[(z0*256 + y1*16 + x1)*CSn + c];
    float v100 = base[(z1*256 + y0*16 + x0)*CSn + c];
    float v101 = base[(z1*256 + y0*16 + x1)*CSn + c];
    float v110 = base[(z1*256 + y1*16 + x0)*CSn + c];
    float v111 = base[(z1*256 + y1*16 + x1)*CSn + c];

    float r0 = (1.f-fy)*((1.f-fx)*v000 + fx*v001) + fy*((1.f-fx)*v010 + fx*v011);
    float r1 = (1.f-fy)*((1.f-fx)*v100 + fx*v101) + fy*((1.f-fx)*v110 + fx*v111);
    g_up_cl[((size_t)b*Pn + p)*CSn + c] = (1.f-fz)*r0 + fz*r1;
}

// -------- 1x1 offset conv: off[b,o,p] = sum_c w[o,c]*cat[b,c,p] ------------
// block: 32 voxels, 256 threads; thread tile 4o x 4v; 6 passes over o.
__global__ void __launch_bounds__(256) k_offset(const float* __restrict__ dst) {
    __shared__ float cat_s[256*32];     // [c][v] 32KB
    int blk = blockIdx.x;               // Bn*(Pn/32)
    int b  = blk / (Pn/32);
    int p0 = (blk % (Pn/32)) * 32;
    int t = threadIdx.x;

    // dst channels 0..127 (coalesced on v)
    for (int i = t; i < 128*32; i += 256) {
        int c = i >> 5, v = i & 31;
        cat_s[i] = dst[((size_t)b*CDn + c)*Pn + p0 + v];
    }
    // up channels 128..255 (coalesced on c; smem write conflicted — cheap)
    for (int i = t; i < 32*128; i += 256) {
        int v = i >> 7, c = i & 127;
        cat_s[(128 + c)*32 + v] = 2.0f * g_up_cl[((size_t)b*Pn + p0 + v)*CSn + c];
    }
    __syncthreads();

    int og = t >> 3, vg = t & 7;
    int v0 = vg * 4;
    for (int pass = 0; pass < 6; ++pass) {
        int o0 = pass*128 + og*4;
        if (o0 >= NOFF) break;
        float4 a0 = {0,0,0,0}, a1 = {0,0,0,0}, a2 = {0,0,0,0}, a3 = {0,0,0,0};
        #pragma unroll 4
        for (int c = 0; c < 256; ++c) {
            float4 wv = *(const float4*)&g_wofft[c*NOFF + o0];
            float4 cv = *(const float4*)&cat_s[c*32 + v0];
            a0.x += wv.x*cv.x; a0.y += wv.x*cv.y; a0.z += wv.x*cv.z; a0.w += wv.x*cv.w;
            a1.x += wv.y*cv.x; a1.y += wv.y*cv.y; a1.z += wv.y*cv.z; a1.w += wv.y*cv.w;
            a2.x += wv.z*cv.x; a2.y += wv.z*cv.y; a2.z += wv.z*cv.z; a2.w += wv.z*cv.w;
            a3.x += wv.w*cv.x; a3.y += wv.w*cv.y; a3.z += wv.w*cv.z; a3.w += wv.w*cv.w;
        }
        size_t ob = ((size_t)b*NOFF + o0)*Pn + p0 + v0;
        *(float4*)&g_off[ob          ] = a0;
        *(float4*)&g_off[ob +   (size_t)Pn] = a1;
        *(float4*)&g_off[ob + 2*(size_t)Pn] = a2;
        *(float4*)&g_off[ob + 3*(size_t)Pn] = a3;
    }
}

// -------- fused deformable sampling + output GEMM + ReLU -------------------
// block: 64 voxels, 256 threads.
// sampling map: thread = (vv = t>>2, q = t&3) -> 4 channels q*4..q*4+3 of group g
// gemm map:     thread = (oc = t>>6, vt = t&63) -> 32 output channels oc*32..+31
__global__ void __launch_bounds__(256) k_dcn(float* __restrict__ out) {
    __shared__ float s_tile[CGn*64];    // [cg][v]
    __shared__ float w_tile[CGn*CDn];   // [cg][o]

    int blk = blockIdx.x;               // Bn*(Pn/64)
    int b  = blk >> 8;
    int p0 = (blk & 255) * 64;
    int t  = threadIdx.x;
    int vv = t >> 2, q = t & 3;
    int vt = t & 63, oc = t >> 6;

    int p = p0 + vv;
    int d = p >> 10, h = (p >> 5) & 31, w = p & 31;

    float4 acc[8];
    #pragma unroll
    for (int j = 0; j < 8; ++j) acc[j] = make_float4(0.f,0.f,0.f,0.f);

    const size_t offB = (size_t)b * NOFF * Pn;

    for (int g = 0; g < Gn; ++g) {
        const float* upg = g_up_cl + (size_t)b*Pn*CSn + g*CGn + q*4;
        for (int k = 0; k < K3n; ++k) {
            int kz = k/9 - 1, ky = (k/3)%3 - 1, kx = k%3 - 1;
            int ob = (g*K3n + k)*3;
            float z = d + kz + g_off[offB + (size_t)(ob+0)*Pn + p];
            float y = h + ky + g_off[offB + (size_t)(ob+1)*Pn + p];
            float x = w + kx + g_off[offB + (size_t)(ob+2)*Pn + p];

            float z0f = floorf(z), y0f = floorf(y), x0f = floorf(x);
            float fz = z - z0f, fy = y - y0f, fx = x - x0f;
            int z0 = (int)z0f, y0 = (int)y0f, x0 = (int)x0f;

            float4 sacc = make_float4(0.f,0.f,0.f,0.f);
            #pragma unroll
            for (int cnr = 0; cnr < 8; ++cnr) {
                int dz = cnr>>2, dy = (cnr>>1)&1, dx = cnr&1;
                int iz = z0+dz, iy = y0+dy, ix = x0+dx;
                float wt = (dz ? fz : 1.f-fz) * (dy ? fy : 1.f-fy) * (dx ? fx : 1.f-fx);
                bool ok = (iz>=0) & (iz<DDn) & (iy>=0) & (iy<DHn) & (ix>=0) & (ix<DWn);
                wt = ok ? wt : 0.f;
                int ci = min(max(iz,0),DDn-1)*1024 + min(max(iy,0),DHn-1)*32 + min(max(ix,0),DWn-1);
                float4 v = *(const float4*)(upg + (size_t)ci*CSn);
                sacc.x += wt*v.x; sacc.y += wt*v.y; sacc.z += wt*v.z; sacc.w += wt*v.w;
            }
            s_tile[(q*4+0)*64 + vv] = sacc.x;
            s_tile[(q*4+1)*64 + vv] = sacc.y;
            s_tile[(q*4+2)*64 + vv] = sacc.z;
            s_tile[(q*4+3)*64 + vv] = sacc.w;

            // stage weight slice [16][128]
            int wbase = (g*K3n + k)*CGn*CDn;
            #pragma unroll
            for (int i = t; i < CGn*CDn; i += 256) w_tile[i] = g_ws[wbase + i];
            __syncthreads();

            #pragma unroll
            for (int cg = 0; cg < CGn; ++cg) {
                float sv = s_tile[cg*64 + vt];
                const float4* wrow = (const float4*)&w_tile[cg*CDn + oc*32];
                #pragma unroll
                for (int j = 0; j < 8; ++j) {
                    float4 wv = wrow[j];
                    acc[j].x += wv.x*sv; acc[j].y += wv.y*sv;
                    acc[j].z += wv.z*sv; acc[j].w += wv.w*sv;
                }
            }
            __syncthreads();
        }
    }

    // ReLU + write out[b][o][p]
    size_t obase = ((size_t)b*CDn + oc*32)*Pn + p0 + vt;
    #pragma unroll
    for (int j = 0; j < 8; ++j) {
        out[obase + (size_t)(j*4+0)*Pn] = fmaxf(acc[j].x, 0.f);
        out[obase + (size_t)(j*4+1)*Pn] = fmaxf(acc[j].y, 0.f);
        out[obase + (size_t)(j*4+2)*Pn] = fmaxf(acc[j].z, 0.f);
        out[obase + (size_t)(j*4+3)*Pn] = fmaxf(acc[j].w, 0.f);
    }
}

extern "C" void kernel_launch(void* const* d_in, const int* in_sizes, int n_in,
                              void* d_out, int out_size) {
    const float* src  = (const float*)d_in[0];   // feat_1x_src [2,128,8,16,16]
    const float* dst  = (const float*)d_in[1];   // feat_2x_dst [2,128,16,32,32]
    const float* woff = (const float*)d_in[2];   // w_offset [648,256]
    const float* wdcn = (const float*)d_in[3];   // w_dcn [128,128,3,3,3]
    float* out = (float*)d_out;

    k_transpose_src <<<(Bn*SDn*SHn*SWn*CSn + 255)/256, 256>>>(src);
    k_transpose_woff<<<(256*NOFF + 255)/256, 256>>>(woff);
    k_transpose_wdcn<<<(Gn*K3n*CGn*CDn + 255)/256, 256>>>(wdcn);
    k_upsample      <<<Bn*Pn, 128>>>();
    k_offset        <<<Bn*(Pn/32), 256>>>(dst);
    k_dcn           <<<Bn*(Pn/64), 256>>>(out);
}

// round 2
// speedup vs baseline: 1.2053x; 1.2053x over previous
#include <cuda_runtime.h>
#include <cstdint>

#define Bn 2
#define CSn 128
#define CDn 128
#define SDn 8
#define SHn 16
#define SWn 16
#define DDn 16
#define DHn 32
#define DWn 32
#define Pn  (DDn*DHn*DWn)      /* 16384 */
#define Gn 8
#define K3n 27
#define CGn 16                 /* CS/G */
#define NOFF (K3n*3*Gn)        /* 648 */

// ---------------- f32x2 helpers (FFMA2 — ptxas never emits from C++) -------
__device__ __forceinline__ unsigned long long ffma2(unsigned long long a,
                                                    unsigned long long b,
                                                    unsigned long long c) {
    unsigned long long d;
    asm("fma.rn.f32x2 %0, %1, %2, %3;" : "=l"(d) : "l"(a), "l"(b), "l"(c));
    return d;
}
__device__ __forceinline__ unsigned long long dup2(float s) {
    unsigned long long d;
    unsigned u = __float_as_uint(s);
    asm("mov.b64 %0, {%1, %1};" : "=l"(d) : "r"(u));
    return d;
}
__device__ __forceinline__ float lo32(unsigned long long v) {
    return __uint_as_float((unsigned)(v & 0xffffffffull));
}
__device__ __forceinline__ float hi32(unsigned long long v) {
    return __uint_as_float((unsigned)(v >> 32));
}

// -------- device scratch (allocation-free rule: __device__ globals) --------
__device__ float g_src_cl[Bn*SDn*SHn*SWn*CSn];   // [b][z][y][x][c]
__device__ float g_up_cl[Bn*Pn*CSn];             // [b][p][c]   (channels-last)
__device__ float g_off[Bn*NOFF*Pn];              // [b][o][p]
__device__ float g_wofft[256*NOFF];              // [c][o]
__device__ float g_ws[Gn*K3n*CGn*CDn];           // [g][k][cg][o]

// -------- prep transposes --------
__global__ void k_transpose_src(const float* __restrict__ src) {
    int i = blockIdx.x * blockDim.x + threadIdx.x;
    const int N = Bn*SDn*SHn*SWn*CSn;
    if (i >= N) return;
    int c = i % CSn;
    int s = (i / CSn) % (SDn*SHn*SWn);
    int b = i / (CSn*SDn*SHn*SWn);
    g_src_cl[i] = src[(b*CSn + c)*(SDn*SHn*SWn) + s];
}

__global__ void k_transpose_woff(const float* __restrict__ w) { // w:[648][256]
    int i = blockIdx.x * blockDim.x + threadIdx.x;
    if (i >= 256*NOFF) return;
    int o = i % NOFF;
    int c = i / NOFF;
    g_wofft[i] = w[o*256 + c];
}

__global__ void k_transpose_wdcn(const float* __restrict__ w) { // w:[o][c][27]
    int i = blockIdx.x * blockDim.x + threadIdx.x;
    if (i >= Gn*K3n*CGn*CDn) return;
    int o  = i % CDn;
    int cg = (i / CDn) % CGn;
    int k  = (i / (CDn*CGn)) % K3n;
    int g  = i / (CDn*CGn*K3n);
    g_ws[i] = w[(o*CSn + g*CGn + cg)*K3n + k];
}

// -------- trilinear 2x upsample (half-pixel, edge-clamped == jax resize) ----
__global__ void k_upsample() {
    int bp = blockIdx.x;                 // Bn*Pn blocks
    int b = bp / Pn;
    int p = bp % Pn;
    int d = p >> 10, h = (p >> 5) & 31, w = p & 31;

    float zc = d*0.5f - 0.25f, yc = h*0.5f - 0.25f, xc = w*0.5f - 0.25f;
    int zf = (int)floorf(zc), yf = (int)floorf(yc), xf = (int)floorf(xc);
    float fz = zc - zf, fy = yc - yf, fx = xc - xf;
    int z0 = min(max(zf,     0), SDn-1), z1 = min(max(zf + 1, 0), SDn-1);
    int y0 = min(max(yf,     0), SHn-1), y1 = min(max(yf + 1, 0), SHn-1);
    int x0 = min(max(xf,     0), SWn-1), x1 = min(max(xf + 1, 0), SWn-1);

    const float* base = g_src_cl + (size_t)b * (SDn*SHn*SWn) * CSn;
    int c = threadIdx.x;  // 128

    float v000 = base[(z0*256 + y0*16 + x0)*CSn + c];
    float v001 = base[(z0*256 + y0*16 + x1)*CSn + c];
    float v010 = base[(z0*256 + y1*16 + x0)*CSn + c];
    float v011 = base[(z0*256 + y1*16 + x1)*CSn + c];
    float v100 = base[(z1*256 + y0*16 + x0)*CSn + c];
    float v101 = base[(z1*256 + y0*16 + x1)*CSn + c];
    float v110 = base[(z1*256 + y1*16 + x0)*CSn + c];
    float v111 = base[(z1*256 + y1*16 + x1)*CSn + c];

    float r0 = (1.f-fy)*((1.f-fx)*v000 + fx*v001) + fy*((1.f-fx)*v010 + fx*v011);
    float r1 = (1.f-fy)*((1.f-fx)*v100 + fx*v101) + fy*((1.f-fx)*v110 + fx*v111);
    g_up_cl[((size_t)b*Pn + p)*CSn + c] = (1.f-fz)*r0 + fz*r1;
}

// -------- 1x1 offset conv: off[b,o,p] = sum_c w[o,c]*cat[b,c,p] ------------
// block: 32 voxels, 256 threads. FFMA2 with output-channel pairs packed.
// thread tile: 8 o (4 o-pairs) x 4 v. 3 passes of 256 o.
__global__ void __launch_bounds__(256) k_offset(const float* __restrict__ dst) {
    __shared__ __align__(16) float cat_s[256*32];     // [c][v] 32KB
    int blk = blockIdx.x;               // Bn*(Pn/32)
    int b  = blk / (Pn/32);
    int p0 = (blk % (Pn/32)) * 32;
    int t = threadIdx.x;

    // dst channels 0..127 (coalesced on v)
    for (int i = t; i < 128*32; i += 256) {
        int c = i >> 5, v = i & 31;
        cat_s[i] = dst[((size_t)b*CDn + c)*Pn + p0 + v];
    }
    // up channels 128..255
    for (int i = t; i < 32*128; i += 256) {
        int v = i >> 7, c = i & 127;
        cat_s[(128 + c)*32 + v] = 2.0f * g_up_cl[((size_t)b*Pn + p0 + v)*CSn + c];
    }
    __syncthreads();

    int og = t >> 3;            // 0..31  -> 8 outputs each
    int vg = t & 7;             // 0..7   -> 4 voxels each
    int v0 = vg * 4;

    #pragma unroll
    for (int pass = 0; pass < 3; ++pass) {
        int o0 = pass*256 + og*8;
        if (o0 >= NOFF) break;             // pass 2: only og<17 active
        unsigned long long a[4][4];
        #pragma unroll
        for (int i = 0; i < 4; ++i)
            #pragma unroll
            for (int j = 0; j < 4; ++j) a[i][j] = 0ull;

        #pragma unroll 4
        for (int c = 0; c < 256; ++c) {
            const ulonglong2* wrow = (const ulonglong2*)&g_wofft[c*NOFF + o0];
            ulonglong2 wA = wrow[0];   // (w[o0],w[o0+1]) , (w[o0+2],w[o0+3])
            ulonglong2 wB = wrow[1];   // (w[o0+4],w[o0+5]), (w[o0+6],w[o0+7])
            float4 sv = *(const float4*)&cat_s[c*32 + v0];
            unsigned long long s0 = dup2(sv.x), s1 = dup2(sv.y);
            unsigned long long s2 = dup2(sv.z), s3 = dup2(sv.w);
            a[0][0] = ffma2(wA.x, s0, a[0][0]); a[0][1] = ffma2(wA.x, s1, a[0][1]);
            a[0][2] = ffma2(wA.x, s2, a[0][2]); a[0][3] = ffma2(wA.x, s3, a[0][3]);
            a[1][0] = ffma2(wA.y, s0, a[1][0]); a[1][1] = ffma2(wA.y, s1, a[1][1]);
            a[1][2] = ffma2(wA.y, s2, a[1][2]); a[1][3] = ffma2(wA.y, s3, a[1][3]);
            a[2][0] = ffma2(wB.x, s0, a[2][0]); a[2][1] = ffma2(wB.x, s1, a[2][1]);
            a[2][2] = ffma2(wB.x, s2, a[2][2]); a[2][3] = ffma2(wB.x, s3, a[2][3]);
            a[3][0] = ffma2(wB.y, s0, a[3][0]); a[3][1] = ffma2(wB.y, s1, a[3][1]);
            a[3][2] = ffma2(wB.y, s2, a[3][2]); a[3][3] = ffma2(wB.y, s3, a[3][3]);
        }

        // per o-pair: lo lane -> o0+2op, hi lane -> o0+2op+1; v contiguous -> float4
        #pragma unroll
        for (int op = 0; op < 4; ++op) {
            float4 flo = make_float4(lo32(a[op][0]), lo32(a[op][1]),
                                     lo32(a[op][2]), lo32(a[op][3]));
            float4 fhi = make_float4(hi32(a[op][0]), hi32(a[op][1]),
                                     hi32(a[op][2]), hi32(a[op][3]));
            size_t base = ((size_t)b*NOFF + o0 + op*2)*Pn + p0 + v0;
            *(float4*)&g_off[base]              = flo;
            *(float4*)&g_off[base + (size_t)Pn] = fhi;
        }
    }
}

// -------- fused deformable sampling + output GEMM + ReLU (FFMA2) -----------
// block: 64 voxels, 256 threads, double-buffered s/w tiles, 1 sync per tap.
// sampling map: (vv = t>>2, q = t&3) -> channels q*4..q*4+3 of group g
// gemm map:     (og = t>>4 -> 8 outs, vg = t&15 -> 4 voxels = 2 packed pairs)
__global__ void __launch_bounds__(256) k_dcn(float* __restrict__ out) {
    __shared__ __align__(16) float  s_tile[2][CGn][64];   // 8KB
    __shared__ __align__(16) float2 wd[2][CGn][CDn];      // 32KB (duplicated w)

    int blk = blockIdx.x;               // Bn*(Pn/64)
    int b  = blk >> 8;
    int p0 = (blk & 255) * 64;
    int t  = threadIdx.x;
    int vv = t >> 2, q = t & 3;
    int og = t >> 4, vg = t & 15;
    int o0 = og * 8, v0 = vg * 4;

    int p = p0 + vv;
    int d = p >> 10, h = (p >> 5) & 31, w = p & 31;

    unsigned long long acc[8][2];
    #pragma unroll
    for (int o = 0; o < 8; ++o) { acc[o][0] = 0ull; acc[o][1] = 0ull; }

    const size_t offB = (size_t)b * NOFF * Pn;
    const float* upB  = g_up_cl + (size_t)b*Pn*CSn;

    // ---- sampling + weight staging for tap kk into buffer buf ----
    auto sample = [&](int kk, int buf) {
        int g = kk / K3n, k = kk % K3n;
        int kz = k/9 - 1, ky = (k/3)%3 - 1, kx = k%3 - 1;
        int ob = (g*K3n + k)*3;
        float z = d + kz + g_off[offB + (size_t)(ob+0)*Pn + p];
        float y = h + ky + g_off[offB + (size_t)(ob+1)*Pn + p];
        float x = w + kx + g_off[offB + (size_t)(ob+2)*Pn + p];

        float z0f = floorf(z), y0f = floorf(y), x0f = floorf(x);
        float fz = z - z0f, fy = y - y0f, fx = x - x0f;
        int z0 = (int)z0f, y0 = (int)y0f, x0 = (int)x0f;

        const float* upg = upB + g*CGn + q*4;
        float4 sacc = make_float4(0.f,0.f,0.f,0.f);
        #pragma unroll
        for (int cnr = 0; cnr < 8; ++cnr) {
            int dz = cnr>>2, dy = (cnr>>1)&1, dx = cnr&1;
            int iz = z0+dz, iy = y0+dy, ix = x0+dx;
            float wt = (dz ? fz : 1.f-fz) * (dy ? fy : 1.f-fy) * (dx ? fx : 1.f-fx);
            bool ok = (iz>=0) & (iz<DDn) & (iy>=0) & (iy<DHn) & (ix>=0) & (ix<DWn);
            wt = ok ? wt : 0.f;
            int ci = min(max(iz,0),DDn-1)*1024 + min(max(iy,0),DHn-1)*32 + min(max(ix,0),DWn-1);
            float4 v = *(const float4*)(upg + (size_t)ci*CSn);
            sacc.x += wt*v.x; sacc.y += wt*v.y; sacc.z += wt*v.z; sacc.w += wt*v.w;
        }
        s_tile[buf][q*4+0][vv] = sacc.x;
        s_tile[buf][q*4+1][vv] = sacc.y;
        s_tile[buf][q*4+2][vv] = sacc.z;
        s_tile[buf][q*4+3][vv] = sacc.w;

        // stage duplicated weight slice [16][128]
        int wbase = kk * (CGn*CDn);
        #pragma unroll
        for (int i = t; i < CGn*CDn; i += 256) {
            float wv = g_ws[wbase + i];
            ((float2*)wd[buf])[i] = make_float2(wv, wv);
        }
    };

    sample(0, 0);
    __syncthreads();

    for (int kk = 0; kk < Gn*K3n; ++kk) {
        int cur = kk & 1;

        // ---- GEMM on buffer cur ----
        #pragma unroll
        for (int cg = 0; cg < CGn; ++cg) {
            ulonglong2 sp = *(const ulonglong2*)&s_tile[cur][cg][v0];
            const ulonglong2* wrow = (const ulonglong2*)&wd[cur][cg][o0];
            ulonglong2 w01 = wrow[0], w23 = wrow[1], w45 = wrow[2], w67 = wrow[3];
            acc[0][0] = ffma2(w01.x, sp.x, acc[0][0]); acc[0][1] = ffma2(w01.x, sp.y, acc[0][1]);
            acc[1][0] = ffma2(w01.y, sp.x, acc[1][0]); acc[1][1] = ffma2(w01.y, sp.y, acc[1][1]);
            acc[2][0] = ffma2(w23.x, sp.x, acc[2][0]); acc[2][1] = ffma2(w23.x, sp.y, acc[2][1]);
            acc[3][0] = ffma2(w23.y, sp.x, acc[3][0]); acc[3][1] = ffma2(w23.y, sp.y, acc[3][1]);
            acc[4][0] = ffma2(w45.x, sp.x, acc[4][0]); acc[4][1] = ffma2(w45.x, sp.y, acc[4][1]);
            acc[5][0] = ffma2(w45.y, sp.x, acc[5][0]); acc[5][1] = ffma2(w45.y, sp.y, acc[5][1]);
            acc[6][0] = ffma2(w67.x, sp.x, acc[6][0]); acc[6][1] = ffma2(w67.x, sp.y, acc[6][1]);
            acc[7][0] = ffma2(w67.y, sp.x, acc[7][0]); acc[7][1] = ffma2(w67.y, sp.y, acc[7][1]);
        }

        if (kk + 1 < Gn*K3n) sample(kk + 1, cur ^ 1);
        __syncthreads();
    }

    // ReLU + write out[b][o][p] as float4 over contiguous voxels
    #pragma unroll
    for (int o = 0; o < 8; ++o) {
        float4 f = make_float4(fmaxf(lo32(acc[o][0]), 0.f),
                               fmaxf(hi32(acc[o][0]), 0.f),
                               fmaxf(lo32(acc[o][1]), 0.f),
                               fmaxf(hi32(acc[o][1]), 0.f));
        *(float4*)&out[((size_t)b*CDn + o0 + o)*Pn + p0 + v0] = f;
    }
}

extern "C" void kernel_launch(void* const* d_in, const int* in_sizes, int n_in,
                              void* d_out, int out_size) {
    const float* src  = (const float*)d_in[0];   // feat_1x_src [2,128,8,16,16]
    const float* dst  = (const float*)d_in[1];   // feat_2x_dst [2,128,16,32,32]
    const float* woff = (const float*)d_in[2];   // w_offset [648,256]
    const float* wdcn = (const float*)d_in[3];   // w_dcn [128,128,3,3,3]
    float* out = (float*)d_out;

    k_transpose_src <<<(Bn*SDn*SHn*SWn*CSn + 255)/256, 256>>>(src);
    k_transpose_woff<<<(256*NOFF + 255)/256, 256>>>(woff);
    k_transpose_wdcn<<<(Gn*K3n*CGn*CDn + 255)/256, 256>>>(wdcn);
    k_upsample      <<<Bn*Pn, 128>>>();
    k_offset        <<<Bn*(Pn/32), 256>>>(dst);
    k_dcn           <<<Bn*(Pn/64), 256>>>(out);
}